// round 12
// baseline (speedup 1.0000x reference)
#include <cuda_runtime.h>
#include <cuda_fp16.h>

#define THREADS 256
#define C16 16
#define DIM 96
#define HW (DIM*DIM)
#define DHW (DIM*DIM*DIM)
#define FEATS 512
#define KTOT 1024
#define NB 8               // fixed brick edge
// padded strides in uint4 (16B) units: x=1, y=10, z=84
// bank-group(16B): (84*dz + 10*dy + dx) mod 8 = {4dz+2dy+dx} mod 8 -> never 0 for |d|<=1
#define SY 10
#define SZ 84
#define PSV (NB*SZ)        // 672 uint4 per channel-octet slab
#define NOCT 2             // 16 channels = 2 octets (uint4 = 4 x half2)
#define BRICK_E (NOCT*PSV) // 1344 uint4 = 21KB

__device__ __forceinline__ void make_corners(
    float w0, float w1, float w2, float sg,
    float bx, float by, float bz,
    float ax0, float ax1, float ax2,
    float ay0, float ay1, float ay2,
    float az0, float az1, float az2,
    int xlo, int ylo, int zlo,
    int* offs, float* wgt)
{
    float px = fmaf(ax0, w0, fmaf(ax1, w1, fmaf(ax2, w2, bx)));
    float py = fmaf(ay0, w0, fmaf(ay1, w1, fmaf(ay2, w2, by)));
    float pz = fmaf(az0, w0, fmaf(az1, w1, fmaf(az2, w2, bz)));
    float fx = floorf(px), fy = floorf(py), fz = floorf(pz);
    float tx = px - fx, ty = py - fy, tz = pz - fz;
    int jx0 = (int)fx - xlo, jy0 = (int)fy - ylo, jz0 = (int)fz - zlo;
    int jx1 = jx0 + 1, jy1 = jy0 + 1, jz1 = jz0 + 1;
    float wx0 = 1.f - tx, wx1 = tx;
    float wy0 = 1.f - ty, wy1 = ty;
    float wz0 = 1.f - tz, wz1 = tz;
    // out-of-brick == out-of-volume: zero weight + clamp index
    if ((unsigned)jx0 >= NB) { wx0 = 0.f; jx0 = 0; }
    if ((unsigned)jx1 >= NB) { wx1 = 0.f; jx1 = 0; }
    if ((unsigned)jy0 >= NB) { wy0 = 0.f; jy0 = 0; }
    if ((unsigned)jy1 >= NB) { wy1 = 0.f; jy1 = 0; }
    if ((unsigned)jz0 >= NB) { wz0 = 0.f; jz0 = 0; }
    if ((unsigned)jz1 >= NB) { wz1 = 0.f; jz1 = 0; }
    float wzy00 = wz0*wy0*sg, wzy01 = wz0*wy1*sg;
    float wzy10 = wz1*wy0*sg, wzy11 = wz1*wy1*sg;
    int r00 = jz0*SZ + jy0*SY, r01 = jz0*SZ + jy1*SY;
    int r10 = jz1*SZ + jy0*SY, r11 = jz1*SZ + jy1*SY;
    offs[0]=r00+jx0; offs[1]=r00+jx1; offs[2]=r01+jx0; offs[3]=r01+jx1;
    offs[4]=r10+jx0; offs[5]=r10+jx1; offs[6]=r11+jx0; offs[7]=r11+jx1;
    wgt[0]=wzy00*wx0; wgt[1]=wzy00*wx1; wgt[2]=wzy01*wx0; wgt[3]=wzy01*wx1;
    wgt[4]=wzy10*wx0; wgt[5]=wzy10*wx1; wgt[6]=wzy11*wx0; wgt[7]=wzy11*wx1;
}

__global__ void __launch_bounds__(THREADS, 2)
obelisk_kernel(const float* __restrict__ vol,
               const float* __restrict__ xyz,
               const float* __restrict__ Amat,
               const float* __restrict__ W6,
               float* __restrict__ out)
{
    __shared__ uint4 brickq[BRICK_E];   // 21KB static
    __shared__ float sP[12];
    __shared__ int   sBox[4];           // xlo,ylo,zlo,mode
    __shared__ float sRed[6*8];

    const int tid  = threadIdx.x;
    const int lane = tid & 31;
    const int wid  = tid >> 5;
    const int pt   = blockIdx.x;        // one block per sample point (KSPLIT=1)
    const int b    = pt >> 9;
    const int f    = pt & (FEATS - 1);

    if (tid == 0) {
        float x0 = xyz[pt*3+0], x1 = xyz[pt*3+1], x2 = xyz[pt*3+2];
        sP[0] = (x0 + 1.f) * 48.f - 0.5f;
        sP[1] = (x1 + 1.f) * 48.f - 0.5f;
        sP[2] = (x2 + 1.f) * 48.f - 0.5f;
        const float* Ar = Amat + pt * 9;
        sP[3] = 48.f*Ar[6]; sP[4]  = 48.f*Ar[7]; sP[5]  = 48.f*Ar[8];  // x row
        sP[6] = 48.f*Ar[3]; sP[7]  = 48.f*Ar[4]; sP[8]  = 48.f*Ar[5];  // y row
        sP[9] = 48.f*Ar[0]; sP[10] = 48.f*Ar[1]; sP[11] = 48.f*Ar[2];  // z row
    }
    __syncthreads();

    const float bx = sP[0], by = sP[1], bz = sP[2];
    const float ax0 = sP[3], ax1 = sP[4],  ax2 = sP[5];
    const float ay0 = sP[6], ay1 = sP[7],  ay2 = sP[8];
    const float az0 = sP[9], az1 = sP[10], az2 = sP[11];

    // ---------------- Pass 1: bbox over all 1024 k (same FP exprs as pass 2)
    float mnx = 1e30f, mxx = -1e30f;
    float mny = 1e30f, mxy = -1e30f;
    float mnz = 1e30f, mxz = -1e30f;
    #pragma unroll
    for (int it = 0; it < 4; it++) {
        int k = it*THREADS + tid;
        #pragma unroll
        for (int s = 0; s < 2; s++) {
            const float* wp = W6 + s*3*KTOT + k;
            float w0 = __ldg(wp);
            float w1 = __ldg(wp + KTOT);
            float w2 = __ldg(wp + 2*KTOT);
            float px = fmaf(ax0, w0, fmaf(ax1, w1, fmaf(ax2, w2, bx)));
            float py = fmaf(ay0, w0, fmaf(ay1, w1, fmaf(ay2, w2, by)));
            float pz = fmaf(az0, w0, fmaf(az1, w1, fmaf(az2, w2, bz)));
            mnx = fminf(mnx, px); mxx = fmaxf(mxx, px);
            mny = fminf(mny, py); mxy = fmaxf(mxy, py);
            mnz = fminf(mnz, pz); mxz = fmaxf(mxz, pz);
        }
    }
    float r0 = mnx, r1 = -mxx, r2 = mny, r3 = -mxy, r4 = mnz, r5 = -mxz;
    #pragma unroll
    for (int o = 16; o > 0; o >>= 1) {
        r0 = fminf(r0, __shfl_xor_sync(0xffffffffu, r0, o));
        r1 = fminf(r1, __shfl_xor_sync(0xffffffffu, r1, o));
        r2 = fminf(r2, __shfl_xor_sync(0xffffffffu, r2, o));
        r3 = fminf(r3, __shfl_xor_sync(0xffffffffu, r3, o));
        r4 = fminf(r4, __shfl_xor_sync(0xffffffffu, r4, o));
        r5 = fminf(r5, __shfl_xor_sync(0xffffffffu, r5, o));
    }
    if (lane == 0) {
        sRed[0*8+wid] = r0; sRed[1*8+wid] = r1; sRed[2*8+wid] = r2;
        sRed[3*8+wid] = r3; sRed[4*8+wid] = r4; sRed[5*8+wid] = r5;
    }
    __syncthreads();
    if (tid == 0) {
        float m0 = sRed[0], m1 = sRed[8], m2 = sRed[16], m3 = sRed[24], m4 = sRed[32], m5 = sRed[40];
        #pragma unroll
        for (int i = 1; i < 8; i++) {
            m0 = fminf(m0, sRed[0*8+i]); m1 = fminf(m1, sRed[1*8+i]);
            m2 = fminf(m2, sRed[2*8+i]); m3 = fminf(m3, sRed[3*8+i]);
            m4 = fminf(m4, sRed[4*8+i]); m5 = fminf(m5, sRed[5*8+i]);
        }
        float MX = -m1, MY = -m3, MZ = -m5;
        int xlo = max(0, (int)floorf(m0));
        int xhi = min(DIM - 1, (int)floorf(MX) + 1);
        int ylo = max(0, (int)floorf(m2));
        int yhi = min(DIM - 1, (int)floorf(MY) + 1);
        int zlo = max(0, (int)floorf(m4));
        int zhi = min(DIM - 1, (int)floorf(MZ) + 1);
        int nx = xhi - xlo + 1, ny = yhi - ylo + 1, nz = zhi - zlo + 1;
        int mode;
        if (nx <= 0 || ny <= 0 || nz <= 0) mode = 2;                   // fully outside
        else if (nx <= NB && ny <= NB && nz <= NB) mode = 0;           // fixed 8^3 brick
        else mode = 1;                                                 // global fallback
        // anchor clamp: brick [lo, lo+7] always inside volume
        sBox[0] = min(xlo, DIM - NB);
        sBox[1] = min(ylo, DIM - NB);
        sBox[2] = min(zlo, DIM - NB);
        sBox[3] = mode;
    }
    __syncthreads();

    const int xlo = sBox[0], ylo = sBox[1], zlo = sBox[2];
    const int mode = sBox[3];

    const size_t out_base0 = (((size_t)b * C16) * FEATS + f) * KTOT;

    if (mode == 2) {
        #pragma unroll
        for (int it = 0; it < 4; it++) {
            int k = it*THREADS + tid;
            #pragma unroll
            for (int c = 0; c < C16; c++)
                out[out_base0 + (size_t)c * (FEATS*KTOT) + k] = 0.f;
        }
        return;
    }

    const float* volb = vol + (size_t)b * C16 * DHW;

    // --- Brick load: 8x8x8 voxels x 2 channel-octets, fp16x8 (uint4) padded layout ---
    if (mode == 0) {
        const float* src = volb + (size_t)zlo * HW + ylo * DIM + xlo;
        #pragma unroll
        for (int t = 0; t < (NOCT*NB*NB*NB) / THREADS; t++) {   // 4 iters
            int m = t * THREADS + tid;
            int x  = m & 7;
            int y  = (m >> 3) & 7;
            int z  = (m >> 6) & 7;
            int c8 = m >> 9;
            const float* s0 = src + (size_t)(8*c8) * DHW + z * HW + y * DIM + x;
            __half2 h0 = __floats2half2_rn(__ldg(s0),         __ldg(s0 + DHW));
            __half2 h1 = __floats2half2_rn(__ldg(s0 + 2*DHW), __ldg(s0 + 3*DHW));
            __half2 h2 = __floats2half2_rn(__ldg(s0 + 4*DHW), __ldg(s0 + 5*DHW));
            __half2 h3 = __floats2half2_rn(__ldg(s0 + 6*DHW), __ldg(s0 + 7*DHW));
            uint4 q;
            q.x = *reinterpret_cast<unsigned int*>(&h0);
            q.y = *reinterpret_cast<unsigned int*>(&h1);
            q.z = *reinterpret_cast<unsigned int*>(&h2);
            q.w = *reinterpret_cast<unsigned int*>(&h3);
            brickq[c8 * PSV + z * SZ + y * SY + x] = q;
        }
    }
    __syncthreads();

    // ---------------- Main sampling loop ----------------
    if (mode == 0) {
        #pragma unroll
        for (int it2 = 0; it2 < 2; it2++) {
            int kA = it2*THREADS + tid;      // k in [0,512)
            int kB = kA + 2*THREADS;         // k + 512
            unsigned long long accA[8], accB[8];
            #pragma unroll
            for (int p = 0; p < 8; p++) { accA[p] = 0ull; accB[p] = 0ull; }

            // batch all 12 weight LDGs
            float wA0a = __ldg(W6 + kA);
            float wA1a = __ldg(W6 + KTOT + kA);
            float wA2a = __ldg(W6 + 2*KTOT + kA);
            float wA0b = __ldg(W6 + 3*KTOT + kA);
            float wA1b = __ldg(W6 + 4*KTOT + kA);
            float wA2b = __ldg(W6 + 5*KTOT + kA);
            float wB0a = __ldg(W6 + kB);
            float wB1a = __ldg(W6 + KTOT + kB);
            float wB2a = __ldg(W6 + 2*KTOT + kB);
            float wB0b = __ldg(W6 + 3*KTOT + kB);
            float wB1b = __ldg(W6 + 4*KTOT + kB);
            float wB2b = __ldg(W6 + 5*KTOT + kB);

            #pragma unroll
            for (int s = 0; s < 2; s++) {
                float sg = s ? -1.f : 1.f;
                int offsA[8]; float wgtA[8];
                int offsB[8]; float wgtB[8];
                make_corners(s ? wA0b : wA0a, s ? wA1b : wA1a, s ? wA2b : wA2a, sg,
                             bx, by, bz, ax0,ax1,ax2, ay0,ay1,ay2, az0,az1,az2,
                             xlo, ylo, zlo, offsA, wgtA);
                make_corners(s ? wB0b : wB0a, s ? wB1b : wB1a, s ? wB2b : wB2a, sg,
                             bx, by, bz, ax0,ax1,ax2, ay0,ay1,ay2, az0,az1,az2,
                             xlo, ylo, zlo, offsB, wgtB);
                #pragma unroll
                for (int j = 0; j < 8; j++) {
                    const uint4* pA = brickq + offsA[j];
                    const uint4* pB = brickq + offsB[j];
                    unsigned long long wpA, wpB;
                    unsigned int wa = __float_as_uint(wgtA[j]);
                    unsigned int wb = __float_as_uint(wgtB[j]);
                    asm("mov.b64 %0, {%1, %1};" : "=l"(wpA) : "r"(wa));
                    asm("mov.b64 %0, {%1, %1};" : "=l"(wpB) : "r"(wb));
                    #pragma unroll
                    for (int c8 = 0; c8 < NOCT; c8++) {
                        uint4 qa = pA[c8 * PSV];
                        uint4 qb = pB[c8 * PSV];
                        // --- kA octet ---
                        {
                            __half2 h0 = *reinterpret_cast<__half2*>(&qa.x);
                            __half2 h1 = *reinterpret_cast<__half2*>(&qa.y);
                            __half2 h2 = *reinterpret_cast<__half2*>(&qa.z);
                            __half2 h3 = *reinterpret_cast<__half2*>(&qa.w);
                            float2 f0 = __half22float2(h0);
                            float2 f1 = __half22float2(h1);
                            float2 f2 = __half22float2(h2);
                            float2 f3 = __half22float2(h3);
                            unsigned long long v0, v1, v2, v3;
                            asm("mov.b64 %0, {%1, %2};" : "=l"(v0) : "f"(f0.x), "f"(f0.y));
                            asm("mov.b64 %0, {%1, %2};" : "=l"(v1) : "f"(f1.x), "f"(f1.y));
                            asm("mov.b64 %0, {%1, %2};" : "=l"(v2) : "f"(f2.x), "f"(f2.y));
                            asm("mov.b64 %0, {%1, %2};" : "=l"(v3) : "f"(f3.x), "f"(f3.y));
                            asm("fma.rn.f32x2 %0, %1, %2, %0;" : "+l"(accA[4*c8])   : "l"(v0), "l"(wpA));
                            asm("fma.rn.f32x2 %0, %1, %2, %0;" : "+l"(accA[4*c8+1]) : "l"(v1), "l"(wpA));
                            asm("fma.rn.f32x2 %0, %1, %2, %0;" : "+l"(accA[4*c8+2]) : "l"(v2), "l"(wpA));
                            asm("fma.rn.f32x2 %0, %1, %2, %0;" : "+l"(accA[4*c8+3]) : "l"(v3), "l"(wpA));
                        }
                        // --- kB octet ---
                        {
                            __half2 h0 = *reinterpret_cast<__half2*>(&qb.x);
                            __half2 h1 = *reinterpret_cast<__half2*>(&qb.y);
                            __half2 h2 = *reinterpret_cast<__half2*>(&qb.z);
                            __half2 h3 = *reinterpret_cast<__half2*>(&qb.w);
                            float2 f0 = __half22float2(h0);
                            float2 f1 = __half22float2(h1);
                            float2 f2 = __half22float2(h2);
                            float2 f3 = __half22float2(h3);
                            unsigned long long v0, v1, v2, v3;
                            asm("mov.b64 %0, {%1, %2};" : "=l"(v0) : "f"(f0.x), "f"(f0.y));
                            asm("mov.b64 %0, {%1, %2};" : "=l"(v1) : "f"(f1.x), "f"(f1.y));
                            asm("mov.b64 %0, {%1, %2};" : "=l"(v2) : "f"(f2.x), "f"(f2.y));
                            asm("mov.b64 %0, {%1, %2};" : "=l"(v3) : "f"(f3.x), "f"(f3.y));
                            asm("fma.rn.f32x2 %0, %1, %2, %0;" : "+l"(accB[4*c8])   : "l"(v0), "l"(wpB));
                            asm("fma.rn.f32x2 %0, %1, %2, %0;" : "+l"(accB[4*c8+1]) : "l"(v1), "l"(wpB));
                            asm("fma.rn.f32x2 %0, %1, %2, %0;" : "+l"(accB[4*c8+2]) : "l"(v2), "l"(wpB));
                            asm("fma.rn.f32x2 %0, %1, %2, %0;" : "+l"(accB[4*c8+3]) : "l"(v3), "l"(wpB));
                        }
                    }
                }
            }
            #pragma unroll
            for (int p = 0; p < 8; p++) {
                float lo, hi;
                asm("mov.b64 {%0, %1}, %2;" : "=f"(lo), "=f"(hi) : "l"(accA[p]));
                out[out_base0 + (size_t)(2*p)   * (FEATS*KTOT) + kA] = lo;
                out[out_base0 + (size_t)(2*p+1) * (FEATS*KTOT) + kA] = hi;
            }
            #pragma unroll
            for (int p = 0; p < 8; p++) {
                float lo, hi;
                asm("mov.b64 {%0, %1}, %2;" : "=f"(lo), "=f"(hi) : "l"(accB[p]));
                out[out_base0 + (size_t)(2*p)   * (FEATS*KTOT) + kB] = lo;
                out[out_base0 + (size_t)(2*p+1) * (FEATS*KTOT) + kB] = hi;
            }
        }
    } else {
        // mode 1: rare oversized bbox -> direct global gathers (full fp32)
        #pragma unroll
        for (int it = 0; it < 4; it++) {
            int k = it*THREADS + tid;
            float acc[C16];
            #pragma unroll
            for (int c = 0; c < C16; c++) acc[c] = 0.f;

            #pragma unroll
            for (int s = 0; s < 2; s++) {
                const float* wp = W6 + s*3*KTOT + k;
                float w0 = __ldg(wp);
                float w1 = __ldg(wp + KTOT);
                float w2 = __ldg(wp + 2*KTOT);
                float px = fmaf(ax0, w0, fmaf(ax1, w1, fmaf(ax2, w2, bx)));
                float py = fmaf(ay0, w0, fmaf(ay1, w1, fmaf(ay2, w2, by)));
                float pz = fmaf(az0, w0, fmaf(az1, w1, fmaf(az2, w2, bz)));
                float fx = floorf(px), fy = floorf(py), fz = floorf(pz);
                float tx = px - fx, ty = py - fy, tz = pz - fz;
                int jx0 = (int)fx, jy0 = (int)fy, jz0 = (int)fz;
                int jx1 = jx0 + 1, jy1 = jy0 + 1, jz1 = jz0 + 1;
                float wx0 = 1.f - tx, wx1 = tx;
                float wy0 = 1.f - ty, wy1 = ty;
                float wz0 = 1.f - tz, wz1 = tz;
                if ((unsigned)jx0 >= (unsigned)DIM) { wx0 = 0.f; jx0 = 0; }
                if ((unsigned)jx1 >= (unsigned)DIM) { wx1 = 0.f; jx1 = 0; }
                if ((unsigned)jy0 >= (unsigned)DIM) { wy0 = 0.f; jy0 = 0; }
                if ((unsigned)jy1 >= (unsigned)DIM) { wy1 = 0.f; jy1 = 0; }
                if ((unsigned)jz0 >= (unsigned)DIM) { wz0 = 0.f; jz0 = 0; }
                if ((unsigned)jz1 >= (unsigned)DIM) { wz1 = 0.f; jz1 = 0; }
                float sg = s ? -1.f : 1.f;
                float wzy00 = wz0*wy0*sg, wzy01 = wz0*wy1*sg;
                float wzy10 = wz1*wy0*sg, wzy11 = wz1*wy1*sg;
                int r00 = jz0*HW + jy0*DIM, r01 = jz0*HW + jy1*DIM;
                int r10 = jz1*HW + jy0*DIM, r11 = jz1*HW + jy1*DIM;
                int offs[8] = { r00+jx0, r00+jx1, r01+jx0, r01+jx1,
                                r10+jx0, r10+jx1, r11+jx0, r11+jx1 };
                float wgt[8] = { wzy00*wx0, wzy00*wx1, wzy01*wx0, wzy01*wx1,
                                 wzy10*wx0, wzy10*wx1, wzy11*wx0, wzy11*wx1 };
                #pragma unroll
                for (int j = 0; j < 8; j++) {
                    const float* pj = volb + offs[j];
                    float w = wgt[j];
                    #pragma unroll
                    for (int c = 0; c < C16; c++)
                        acc[c] = fmaf(w, __ldg(pj + (size_t)c * DHW), acc[c]);
                }
            }
            #pragma unroll
            for (int c = 0; c < C16; c++)
                out[out_base0 + (size_t)c * (FEATS*KTOT) + k] = acc[c];
        }
    }
}

extern "C" void kernel_launch(void* const* d_in, const int* in_sizes, int n_in,
                              void* d_out, int out_size)
{
    const float* vol  = (const float*)d_in[0];  // [2,16,96,96,96]
    const float* xyz  = (const float*)d_in[1];  // [2,512,3]
    const float* Amat = (const float*)d_in[2];  // [1024,3,3]
    const float* W6   = (const float*)d_in[3];  // [6,1024]
    float* out = (float*)d_out;                 // [2, 16*512, 1024]

    const int nblocks = 2 * FEATS;              // 1024 (one per sample point)
    obelisk_kernel<<<nblocks, THREADS>>>(vol, xyz, Amat, W6, out);
}

// round 13
// speedup vs baseline: 1.0074x; 1.0074x over previous
#include <cuda_runtime.h>
#include <cuda_fp16.h>

#define THREADS 256
#define C16 16
#define DIM 96
#define HW (DIM*DIM)
#define DHW (DIM*DIM*DIM)
#define FEATS 512
#define KTOT 1024
#define NB 8               // fixed brick edge
// padded strides in uint4 (16B) units: x=1, y=10, z=84
// bank-group(16B): (84*dz + 10*dy + dx) mod 8 = {4dz+2dy+dx} mod 8 -> never 0 for |d|<=1
#define SY 10
#define SZ 84
#define PSV (NB*SZ)        // 672 uint4 per channel-octet slab
#define NOCT 2             // 16 channels = 2 octets (uint4 = 4 x half2)
#define BRICK_E (NOCT*PSV) // 1344 uint4 = 21KB

__global__ void __launch_bounds__(THREADS, 3)
obelisk_kernel(const float* __restrict__ vol,
               const float* __restrict__ xyz,
               const float* __restrict__ Amat,
               const float* __restrict__ W6,
               float* __restrict__ out)
{
    __shared__ uint4 brickq[BRICK_E];   // 21KB static
    __shared__ float sP[12];
    __shared__ int   sBox[4];           // xlo,ylo,zlo,mode
    __shared__ float sRed[6*8];

    const int tid  = threadIdx.x;
    const int lane = tid & 31;
    const int wid  = tid >> 5;
    const int pt   = blockIdx.x;        // one block per sample point (KSPLIT=1)
    const int b    = pt >> 9;
    const int f    = pt & (FEATS - 1);

    if (tid == 0) {
        float x0 = xyz[pt*3+0], x1 = xyz[pt*3+1], x2 = xyz[pt*3+2];
        sP[0] = (x0 + 1.f) * 48.f - 0.5f;
        sP[1] = (x1 + 1.f) * 48.f - 0.5f;
        sP[2] = (x2 + 1.f) * 48.f - 0.5f;
        const float* Ar = Amat + pt * 9;
        sP[3] = 48.f*Ar[6]; sP[4]  = 48.f*Ar[7]; sP[5]  = 48.f*Ar[8];  // x row
        sP[6] = 48.f*Ar[3]; sP[7]  = 48.f*Ar[4]; sP[8]  = 48.f*Ar[5];  // y row
        sP[9] = 48.f*Ar[0]; sP[10] = 48.f*Ar[1]; sP[11] = 48.f*Ar[2];  // z row
    }
    __syncthreads();

    const float bx = sP[0], by = sP[1], bz = sP[2];
    const float ax0 = sP[3], ax1 = sP[4],  ax2 = sP[5];
    const float ay0 = sP[6], ay1 = sP[7],  ay2 = sP[8];
    const float az0 = sP[9], az1 = sP[10], az2 = sP[11];

    // ---------------- Pass 1: bbox over all 1024 k (same FP exprs as pass 2)
    float mnx = 1e30f, mxx = -1e30f;
    float mny = 1e30f, mxy = -1e30f;
    float mnz = 1e30f, mxz = -1e30f;
    #pragma unroll
    for (int it = 0; it < 4; it++) {
        int k = it*THREADS + tid;
        #pragma unroll
        for (int s = 0; s < 2; s++) {
            const float* wp = W6 + s*3*KTOT + k;
            float w0 = __ldg(wp);
            float w1 = __ldg(wp + KTOT);
            float w2 = __ldg(wp + 2*KTOT);
            float px = fmaf(ax0, w0, fmaf(ax1, w1, fmaf(ax2, w2, bx)));
            float py = fmaf(ay0, w0, fmaf(ay1, w1, fmaf(ay2, w2, by)));
            float pz = fmaf(az0, w0, fmaf(az1, w1, fmaf(az2, w2, bz)));
            mnx = fminf(mnx, px); mxx = fmaxf(mxx, px);
            mny = fminf(mny, py); mxy = fmaxf(mxy, py);
            mnz = fminf(mnz, pz); mxz = fmaxf(mxz, pz);
        }
    }
    float r0 = mnx, r1 = -mxx, r2 = mny, r3 = -mxy, r4 = mnz, r5 = -mxz;
    #pragma unroll
    for (int o = 16; o > 0; o >>= 1) {
        r0 = fminf(r0, __shfl_xor_sync(0xffffffffu, r0, o));
        r1 = fminf(r1, __shfl_xor_sync(0xffffffffu, r1, o));
        r2 = fminf(r2, __shfl_xor_sync(0xffffffffu, r2, o));
        r3 = fminf(r3, __shfl_xor_sync(0xffffffffu, r3, o));
        r4 = fminf(r4, __shfl_xor_sync(0xffffffffu, r4, o));
        r5 = fminf(r5, __shfl_xor_sync(0xffffffffu, r5, o));
    }
    if (lane == 0) {
        sRed[0*8+wid] = r0; sRed[1*8+wid] = r1; sRed[2*8+wid] = r2;
        sRed[3*8+wid] = r3; sRed[4*8+wid] = r4; sRed[5*8+wid] = r5;
    }
    __syncthreads();
    if (tid == 0) {
        float m0 = sRed[0], m1 = sRed[8], m2 = sRed[16], m3 = sRed[24], m4 = sRed[32], m5 = sRed[40];
        #pragma unroll
        for (int i = 1; i < 8; i++) {
            m0 = fminf(m0, sRed[0*8+i]); m1 = fminf(m1, sRed[1*8+i]);
            m2 = fminf(m2, sRed[2*8+i]); m3 = fminf(m3, sRed[3*8+i]);
            m4 = fminf(m4, sRed[4*8+i]); m5 = fminf(m5, sRed[5*8+i]);
        }
        float MX = -m1, MY = -m3, MZ = -m5;
        int xlo = max(0, (int)floorf(m0));
        int xhi = min(DIM - 1, (int)floorf(MX) + 1);
        int ylo = max(0, (int)floorf(m2));
        int yhi = min(DIM - 1, (int)floorf(MY) + 1);
        int zlo = max(0, (int)floorf(m4));
        int zhi = min(DIM - 1, (int)floorf(MZ) + 1);
        int nx = xhi - xlo + 1, ny = yhi - ylo + 1, nz = zhi - zlo + 1;
        int mode;
        if (nx <= 0 || ny <= 0 || nz <= 0) mode = 2;                   // fully outside
        else if (nx <= NB && ny <= NB && nz <= NB) mode = 0;           // fixed 8^3 brick
        else mode = 1;                                                 // global fallback
        // anchor clamp: brick [lo, lo+7] always inside volume
        sBox[0] = min(xlo, DIM - NB);
        sBox[1] = min(ylo, DIM - NB);
        sBox[2] = min(zlo, DIM - NB);
        sBox[3] = mode;
    }
    __syncthreads();

    const int xlo = sBox[0], ylo = sBox[1], zlo = sBox[2];
    const int mode = sBox[3];

    const size_t out_base0 = (((size_t)b * C16) * FEATS + f) * KTOT;

    if (mode == 2) {
        #pragma unroll
        for (int it = 0; it < 4; it++) {
            int k = it*THREADS + tid;
            #pragma unroll
            for (int c = 0; c < C16; c++)
                out[out_base0 + (size_t)c * (FEATS*KTOT) + k] = 0.f;
        }
        return;
    }

    const float* volb = vol + (size_t)b * C16 * DHW;

    // --- Brick load: 8x8x8 voxels x 2 channel-octets, fp16x8 (uint4) padded layout ---
    if (mode == 0) {
        const float* src = volb + (size_t)zlo * HW + ylo * DIM + xlo;
        #pragma unroll
        for (int t = 0; t < (NOCT*NB*NB*NB) / THREADS; t++) {   // 4 iters
            int m = t * THREADS + tid;
            int x  = m & 7;
            int y  = (m >> 3) & 7;
            int z  = (m >> 6) & 7;
            int c8 = m >> 9;
            const float* s0 = src + (size_t)(8*c8) * DHW + z * HW + y * DIM + x;
            __half2 h0 = __floats2half2_rn(__ldg(s0),         __ldg(s0 + DHW));
            __half2 h1 = __floats2half2_rn(__ldg(s0 + 2*DHW), __ldg(s0 + 3*DHW));
            __half2 h2 = __floats2half2_rn(__ldg(s0 + 4*DHW), __ldg(s0 + 5*DHW));
            __half2 h3 = __floats2half2_rn(__ldg(s0 + 6*DHW), __ldg(s0 + 7*DHW));
            uint4 q;
            q.x = *reinterpret_cast<unsigned int*>(&h0);
            q.y = *reinterpret_cast<unsigned int*>(&h1);
            q.z = *reinterpret_cast<unsigned int*>(&h2);
            q.w = *reinterpret_cast<unsigned int*>(&h3);
            brickq[c8 * PSV + z * SZ + y * SY + x] = q;
        }
    }
    __syncthreads();

    // ---------------- Main sampling loop ----------------
    if (mode == 0) {
        #pragma unroll 2
        for (int it = 0; it < 4; it++) {
            int k = it*THREADS + tid;
            // 16 fp32 accumulators held as 8 packed f32x2 (64-bit) regs
            unsigned long long acc64[8];
            #pragma unroll
            for (int p = 0; p < 8; p++) acc64[p] = 0ull;

            // load all 6 offset weights up front (batch both LDG latencies)
            float w0a = __ldg(W6 + k);
            float w1a = __ldg(W6 + KTOT + k);
            float w2a = __ldg(W6 + 2*KTOT + k);
            float w0b = __ldg(W6 + 3*KTOT + k);
            float w1b = __ldg(W6 + 4*KTOT + k);
            float w2b = __ldg(W6 + 5*KTOT + k);

            #pragma unroll
            for (int s = 0; s < 2; s++) {
                float w0 = s ? w0b : w0a;
                float w1 = s ? w1b : w1a;
                float w2 = s ? w2b : w2a;
                float px = fmaf(ax0, w0, fmaf(ax1, w1, fmaf(ax2, w2, bx)));
                float py = fmaf(ay0, w0, fmaf(ay1, w1, fmaf(ay2, w2, by)));
                float pz = fmaf(az0, w0, fmaf(az1, w1, fmaf(az2, w2, bz)));
                float fx = floorf(px), fy = floorf(py), fz = floorf(pz);
                float tx = px - fx, ty = py - fy, tz = pz - fz;
                int jx0 = (int)fx - xlo, jy0 = (int)fy - ylo, jz0 = (int)fz - zlo;
                int jx1 = jx0 + 1, jy1 = jy0 + 1, jz1 = jz0 + 1;
                float wx0 = 1.f - tx, wx1 = tx;
                float wy0 = 1.f - ty, wy1 = ty;
                float wz0 = 1.f - tz, wz1 = tz;
                // out-of-brick == out-of-volume: zero weight + clamp index
                if ((unsigned)jx0 >= NB) { wx0 = 0.f; jx0 = 0; }
                if ((unsigned)jx1 >= NB) { wx1 = 0.f; jx1 = 0; }
                if ((unsigned)jy0 >= NB) { wy0 = 0.f; jy0 = 0; }
                if ((unsigned)jy1 >= NB) { wy1 = 0.f; jy1 = 0; }
                if ((unsigned)jz0 >= NB) { wz0 = 0.f; jz0 = 0; }
                if ((unsigned)jz1 >= NB) { wz1 = 0.f; jz1 = 0; }
                float sg = s ? -1.f : 1.f;
                float wzy00 = wz0*wy0*sg, wzy01 = wz0*wy1*sg;
                float wzy10 = wz1*wy0*sg, wzy11 = wz1*wy1*sg;
                int r00 = jz0*SZ + jy0*SY, r01 = jz0*SZ + jy1*SY;
                int r10 = jz1*SZ + jy0*SY, r11 = jz1*SZ + jy1*SY;
                int offs[8] = { r00+jx0, r00+jx1, r01+jx0, r01+jx1,
                                r10+jx0, r10+jx1, r11+jx0, r11+jx1 };
                float wgt[8] = { wzy00*wx0, wzy00*wx1, wzy01*wx0, wzy01*wx1,
                                 wzy10*wx0, wzy10*wx1, wzy11*wx0, wzy11*wx1 };
                #pragma unroll
                for (int j = 0; j < 8; j++) {
                    const uint4* pj = brickq + offs[j];   // one address per corner
                    unsigned long long w2pk;
                    unsigned int wbits = __float_as_uint(wgt[j]);
                    asm("mov.b64 %0, {%1, %1};" : "=l"(w2pk) : "r"(wbits));
                    #pragma unroll
                    for (int c8 = 0; c8 < NOCT; c8++) {   // LDS.128, immediate c8*PSV*16
                        uint4 q = pj[c8 * PSV];
                        __half2 h0 = *reinterpret_cast<__half2*>(&q.x);
                        __half2 h1 = *reinterpret_cast<__half2*>(&q.y);
                        __half2 h2 = *reinterpret_cast<__half2*>(&q.z);
                        __half2 h3 = *reinterpret_cast<__half2*>(&q.w);
                        float2 f0 = __half22float2(h0);
                        float2 f1 = __half22float2(h1);
                        float2 f2 = __half22float2(h2);
                        float2 f3 = __half22float2(h3);
                        unsigned long long v0, v1, v2, v3;
                        asm("mov.b64 %0, {%1, %2};" : "=l"(v0) : "f"(f0.x), "f"(f0.y));
                        asm("mov.b64 %0, {%1, %2};" : "=l"(v1) : "f"(f1.x), "f"(f1.y));
                        asm("mov.b64 %0, {%1, %2};" : "=l"(v2) : "f"(f2.x), "f"(f2.y));
                        asm("mov.b64 %0, {%1, %2};" : "=l"(v3) : "f"(f3.x), "f"(f3.y));
                        asm("fma.rn.f32x2 %0, %1, %2, %0;" : "+l"(acc64[4*c8])   : "l"(v0), "l"(w2pk));
                        asm("fma.rn.f32x2 %0, %1, %2, %0;" : "+l"(acc64[4*c8+1]) : "l"(v1), "l"(w2pk));
                        asm("fma.rn.f32x2 %0, %1, %2, %0;" : "+l"(acc64[4*c8+2]) : "l"(v2), "l"(w2pk));
                        asm("fma.rn.f32x2 %0, %1, %2, %0;" : "+l"(acc64[4*c8+3]) : "l"(v3), "l"(w2pk));
                    }
                }
            }
            #pragma unroll
            for (int p = 0; p < 8; p++) {
                float lo, hi;
                asm("mov.b64 {%0, %1}, %2;" : "=f"(lo), "=f"(hi) : "l"(acc64[p]));
                out[out_base0 + (size_t)(2*p)   * (FEATS*KTOT) + k] = lo;
                out[out_base0 + (size_t)(2*p+1) * (FEATS*KTOT) + k] = hi;
            }
        }
    } else {
        // mode 1: rare oversized bbox -> direct global gathers (full fp32)
        #pragma unroll 1
        for (int it = 0; it < 4; it++) {
            int k = it*THREADS + tid;
            float acc[C16];
            #pragma unroll
            for (int c = 0; c < C16; c++) acc[c] = 0.f;

            #pragma unroll
            for (int s = 0; s < 2; s++) {
                const float* wp = W6 + s*3*KTOT + k;
                float w0 = __ldg(wp);
                float w1 = __ldg(wp + KTOT);
                float w2 = __ldg(wp + 2*KTOT);
                float px = fmaf(ax0, w0, fmaf(ax1, w1, fmaf(ax2, w2, bx)));
                float py = fmaf(ay0, w0, fmaf(ay1, w1, fmaf(ay2, w2, by)));
                float pz = fmaf(az0, w0, fmaf(az1, w1, fmaf(az2, w2, bz)));
                float fx = floorf(px), fy = floorf(py), fz = floorf(pz);
                float tx = px - fx, ty = py - fy, tz = pz - fz;
                int jx0 = (int)fx, jy0 = (int)fy, jz0 = (int)fz;
                int jx1 = jx0 + 1, jy1 = jy0 + 1, jz1 = jz0 + 1;
                float wx0 = 1.f - tx, wx1 = tx;
                float wy0 = 1.f - ty, wy1 = ty;
                float wz0 = 1.f - tz, wz1 = tz;
                if ((unsigned)jx0 >= (unsigned)DIM) { wx0 = 0.f; jx0 = 0; }
                if ((unsigned)jx1 >= (unsigned)DIM) { wx1 = 0.f; jx1 = 0; }
                if ((unsigned)jy0 >= (unsigned)DIM) { wy0 = 0.f; jy0 = 0; }
                if ((unsigned)jy1 >= (unsigned)DIM) { wy1 = 0.f; jy1 = 0; }
                if ((unsigned)jz0 >= (unsigned)DIM) { wz0 = 0.f; jz0 = 0; }
                if ((unsigned)jz1 >= (unsigned)DIM) { wz1 = 0.f; jz1 = 0; }
                float sg = s ? -1.f : 1.f;
                float wzy00 = wz0*wy0*sg, wzy01 = wz0*wy1*sg;
                float wzy10 = wz1*wy0*sg, wzy11 = wz1*wy1*sg;
                int r00 = jz0*HW + jy0*DIM, r01 = jz0*HW + jy1*DIM;
                int r10 = jz1*HW + jy0*DIM, r11 = jz1*HW + jy1*DIM;
                int offs[8] = { r00+jx0, r00+jx1, r01+jx0, r01+jx1,
                                r10+jx0, r10+jx1, r11+jx0, r11+jx1 };
                float wgt[8] = { wzy00*wx0, wzy00*wx1, wzy01*wx0, wzy01*wx1,
                                 wzy10*wx0, wzy10*wx1, wzy11*wx0, wzy11*wx1 };
                #pragma unroll
                for (int j = 0; j < 8; j++) {
                    const float* pj = volb + offs[j];
                    float w = wgt[j];
                    #pragma unroll
                    for (int c = 0; c < C16; c++)
                        acc[c] = fmaf(w, __ldg(pj + (size_t)c * DHW), acc[c]);
                }
            }
            #pragma unroll
            for (int c = 0; c < C16; c++)
                out[out_base0 + (size_t)c * (FEATS*KTOT) + k] = acc[c];
        }
    }
}

extern "C" void kernel_launch(void* const* d_in, const int* in_sizes, int n_in,
                              void* d_out, int out_size)
{
    const float* vol  = (const float*)d_in[0];  // [2,16,96,96,96]
    const float* xyz  = (const float*)d_in[1];  // [2,512,3]
    const float* Amat = (const float*)d_in[2];  // [1024,3,3]
    const float* W6   = (const float*)d_in[3];  // [6,1024]
    float* out = (float*)d_out;                 // [2, 16*512, 1024]

    const int nblocks = 2 * FEATS;              // 1024 (one per sample point)
    obelisk_kernel<<<nblocks, THREADS>>>(vol, xyz, Amat, W6, out);
}

// round 14
// speedup vs baseline: 1.1429x; 1.1345x over previous
#include <cuda_runtime.h>
#include <cuda_fp16.h>

#define THREADS 256
#define C16 16
#define DIM 96
#define HW (DIM*DIM)
#define DHW (DIM*DIM*DIM)
#define FEATS 512
#define KTOT 1024
#define KPB 512            // k per block (KSPLIT=2)
#define NB 8               // fixed brick edge
// padded strides in uint4 (16B) units: x=1, y=10, z=84
// bank-group(16B): (84*dz + 10*dy + dx) mod 8 = {4dz+2dy+dx} mod 8 -> never 0 for |d|<=1
#define SY 10
#define SZ 84
#define PSV (NB*SZ)        // 672 uint4 per channel-octet slab
#define NOCT 2             // 16 channels = 2 octets (uint4 = 4 x half2)
#define BRICK_E (NOCT*PSV) // 1344 uint4 = 21KB

__global__ void __launch_bounds__(THREADS, 3)
obelisk_kernel(const float* __restrict__ vol,
               const float* __restrict__ xyz,
               const float* __restrict__ Amat,
               const float* __restrict__ W6,
               float* __restrict__ out)
{
    __shared__ uint4 brickq[BRICK_E];   // 21KB static
    __shared__ float sP[12];
    __shared__ int   sBox[4];           // xlo,ylo,zlo,mode
    __shared__ float sRed[6*8];

    const int tid  = threadIdx.x;
    const int lane = tid & 31;
    const int wid  = tid >> 5;
    const int blk  = blockIdx.x;
    const int pt   = blk >> 1;
    const int kh   = blk & 1;
    const int b    = pt >> 9;
    const int f    = pt & (FEATS - 1);
    const int k0   = kh * KPB;

    if (tid == 0) {
        float x0 = xyz[pt*3+0], x1 = xyz[pt*3+1], x2 = xyz[pt*3+2];
        sP[0] = (x0 + 1.f) * 48.f - 0.5f;
        sP[1] = (x1 + 1.f) * 48.f - 0.5f;
        sP[2] = (x2 + 1.f) * 48.f - 0.5f;
        const float* Ar = Amat + pt * 9;
        sP[3] = 48.f*Ar[6]; sP[4]  = 48.f*Ar[7]; sP[5]  = 48.f*Ar[8];  // x row
        sP[6] = 48.f*Ar[3]; sP[7]  = 48.f*Ar[4]; sP[8]  = 48.f*Ar[5];  // y row
        sP[9] = 48.f*Ar[0]; sP[10] = 48.f*Ar[1]; sP[11] = 48.f*Ar[2];  // z row
    }
    __syncthreads();

    const float bx = sP[0], by = sP[1], bz = sP[2];
    const float ax0 = sP[3], ax1 = sP[4],  ax2 = sP[5];
    const float ay0 = sP[6], ay1 = sP[7],  ay2 = sP[8];
    const float az0 = sP[9], az1 = sP[10], az2 = sP[11];

    // ---------------- Pass 1: bbox of this block's 512 k (same FP exprs as pass 2)
    float mnx = 1e30f, mxx = -1e30f;
    float mny = 1e30f, mxy = -1e30f;
    float mnz = 1e30f, mxz = -1e30f;
    #pragma unroll
    for (int it = 0; it < 2; it++) {
        int k = k0 + it*THREADS + tid;
        #pragma unroll
        for (int s = 0; s < 2; s++) {
            const float* wp = W6 + s*3*KTOT + k;
            float w0 = __ldg(wp);
            float w1 = __ldg(wp + KTOT);
            float w2 = __ldg(wp + 2*KTOT);
            float px = fmaf(ax0, w0, fmaf(ax1, w1, fmaf(ax2, w2, bx)));
            float py = fmaf(ay0, w0, fmaf(ay1, w1, fmaf(ay2, w2, by)));
            float pz = fmaf(az0, w0, fmaf(az1, w1, fmaf(az2, w2, bz)));
            mnx = fminf(mnx, px); mxx = fmaxf(mxx, px);
            mny = fminf(mny, py); mxy = fmaxf(mxy, py);
            mnz = fminf(mnz, pz); mxz = fmaxf(mxz, pz);
        }
    }
    float r0 = mnx, r1 = -mxx, r2 = mny, r3 = -mxy, r4 = mnz, r5 = -mxz;
    #pragma unroll
    for (int o = 16; o > 0; o >>= 1) {
        r0 = fminf(r0, __shfl_xor_sync(0xffffffffu, r0, o));
        r1 = fminf(r1, __shfl_xor_sync(0xffffffffu, r1, o));
        r2 = fminf(r2, __shfl_xor_sync(0xffffffffu, r2, o));
        r3 = fminf(r3, __shfl_xor_sync(0xffffffffu, r3, o));
        r4 = fminf(r4, __shfl_xor_sync(0xffffffffu, r4, o));
        r5 = fminf(r5, __shfl_xor_sync(0xffffffffu, r5, o));
    }
    if (lane == 0) {
        sRed[0*8+wid] = r0; sRed[1*8+wid] = r1; sRed[2*8+wid] = r2;
        sRed[3*8+wid] = r3; sRed[4*8+wid] = r4; sRed[5*8+wid] = r5;
    }
    __syncthreads();
    if (tid == 0) {
        float m0 = sRed[0], m1 = sRed[8], m2 = sRed[16], m3 = sRed[24], m4 = sRed[32], m5 = sRed[40];
        #pragma unroll
        for (int i = 1; i < 8; i++) {
            m0 = fminf(m0, sRed[0*8+i]); m1 = fminf(m1, sRed[1*8+i]);
            m2 = fminf(m2, sRed[2*8+i]); m3 = fminf(m3, sRed[3*8+i]);
            m4 = fminf(m4, sRed[4*8+i]); m5 = fminf(m5, sRed[5*8+i]);
        }
        float MX = -m1, MY = -m3, MZ = -m5;
        int xlo = max(0, (int)floorf(m0));
        int xhi = min(DIM - 1, (int)floorf(MX) + 1);
        int ylo = max(0, (int)floorf(m2));
        int yhi = min(DIM - 1, (int)floorf(MY) + 1);
        int zlo = max(0, (int)floorf(m4));
        int zhi = min(DIM - 1, (int)floorf(MZ) + 1);
        int nx = xhi - xlo + 1, ny = yhi - ylo + 1, nz = zhi - zlo + 1;
        int mode;
        if (nx <= 0 || ny <= 0 || nz <= 0) mode = 2;                   // fully outside
        else if (nx <= NB && ny <= NB && nz <= NB) mode = 0;           // fixed 8^3 brick
        else mode = 1;                                                 // global fallback
        // anchor clamp: brick [lo, lo+7] always inside volume
        sBox[0] = min(xlo, DIM - NB);
        sBox[1] = min(ylo, DIM - NB);
        sBox[2] = min(zlo, DIM - NB);
        sBox[3] = mode;
    }
    __syncthreads();

    const int xlo = sBox[0], ylo = sBox[1], zlo = sBox[2];
    const int mode = sBox[3];

    const size_t out_base0 = (((size_t)b * C16) * FEATS + f) * KTOT;

    if (mode == 2) {
        #pragma unroll
        for (int it = 0; it < 2; it++) {
            int k = k0 + it*THREADS + tid;
            #pragma unroll
            for (int c = 0; c < C16; c++)
                out[out_base0 + (size_t)c * (FEATS*KTOT) + k] = 0.f;
        }
        return;
    }

    const float* volb = vol + (size_t)b * C16 * DHW;

    // --- Brick load: 8x8x8 voxels x 2 channel-octets, fp16x8 (uint4) padded layout ---
    if (mode == 0) {
        const float* src = volb + (size_t)zlo * HW + ylo * DIM + xlo;
        #pragma unroll
        for (int t = 0; t < (NOCT*NB*NB*NB) / THREADS; t++) {   // 4 iters
            int m = t * THREADS + tid;
            int x  = m & 7;
            int y  = (m >> 3) & 7;
            int z  = (m >> 6) & 7;
            int c8 = m >> 9;
            const float* s0 = src + (size_t)(8*c8) * DHW + z * HW + y * DIM + x;
            __half2 h0 = __floats2half2_rn(__ldg(s0),         __ldg(s0 + DHW));
            __half2 h1 = __floats2half2_rn(__ldg(s0 + 2*DHW), __ldg(s0 + 3*DHW));
            __half2 h2 = __floats2half2_rn(__ldg(s0 + 4*DHW), __ldg(s0 + 5*DHW));
            __half2 h3 = __floats2half2_rn(__ldg(s0 + 6*DHW), __ldg(s0 + 7*DHW));
            uint4 q;
            q.x = *reinterpret_cast<unsigned int*>(&h0);
            q.y = *reinterpret_cast<unsigned int*>(&h1);
            q.z = *reinterpret_cast<unsigned int*>(&h2);
            q.w = *reinterpret_cast<unsigned int*>(&h3);
            brickq[c8 * PSV + z * SZ + y * SY + x] = q;
        }
    }
    __syncthreads();

    // ---------------- Main sampling loop ----------------
    if (mode == 0) {
        #pragma unroll
        for (int it = 0; it < 2; it++) {
            int k = k0 + it*THREADS + tid;
            // 16 fp32 accumulators held as 8 packed f32x2 (64-bit) regs
            unsigned long long acc64[8];
            #pragma unroll
            for (int p = 0; p < 8; p++) acc64[p] = 0ull;

            // load all 6 offset weights up front (batch both LDG latencies)
            float w0a = __ldg(W6 + k);
            float w1a = __ldg(W6 + KTOT + k);
            float w2a = __ldg(W6 + 2*KTOT + k);
            float w0b = __ldg(W6 + 3*KTOT + k);
            float w1b = __ldg(W6 + 4*KTOT + k);
            float w2b = __ldg(W6 + 5*KTOT + k);

            // ---- compute BOTH s-streams' corner sets up front ----
            // offsets packed 2-per-int (s0 in low 16, s1 in high 16)
            int   offsPk[8];
            float wgt0[8], wgt1[8];
            #pragma unroll
            for (int s = 0; s < 2; s++) {
                float w0 = s ? w0b : w0a;
                float w1 = s ? w1b : w1a;
                float w2 = s ? w2b : w2a;
                float px = fmaf(ax0, w0, fmaf(ax1, w1, fmaf(ax2, w2, bx)));
                float py = fmaf(ay0, w0, fmaf(ay1, w1, fmaf(ay2, w2, by)));
                float pz = fmaf(az0, w0, fmaf(az1, w1, fmaf(az2, w2, bz)));
                float fx = floorf(px), fy = floorf(py), fz = floorf(pz);
                float tx = px - fx, ty = py - fy, tz = pz - fz;
                int jx0 = (int)fx - xlo, jy0 = (int)fy - ylo, jz0 = (int)fz - zlo;
                int jx1 = jx0 + 1, jy1 = jy0 + 1, jz1 = jz0 + 1;
                float wx0 = 1.f - tx, wx1 = tx;
                float wy0 = 1.f - ty, wy1 = ty;
                float wz0 = 1.f - tz, wz1 = tz;
                // out-of-brick == out-of-volume: zero weight + clamp index
                if ((unsigned)jx0 >= NB) { wx0 = 0.f; jx0 = 0; }
                if ((unsigned)jx1 >= NB) { wx1 = 0.f; jx1 = 0; }
                if ((unsigned)jy0 >= NB) { wy0 = 0.f; jy0 = 0; }
                if ((unsigned)jy1 >= NB) { wy1 = 0.f; jy1 = 0; }
                if ((unsigned)jz0 >= NB) { wz0 = 0.f; jz0 = 0; }
                if ((unsigned)jz1 >= NB) { wz1 = 0.f; jz1 = 0; }
                float sg = s ? -1.f : 1.f;
                float wzy00 = wz0*wy0*sg, wzy01 = wz0*wy1*sg;
                float wzy10 = wz1*wy0*sg, wzy11 = wz1*wy1*sg;
                int r00 = jz0*SZ + jy0*SY, r01 = jz0*SZ + jy1*SY;
                int r10 = jz1*SZ + jy0*SY, r11 = jz1*SZ + jy1*SY;
                int o[8] = { r00+jx0, r00+jx1, r01+jx0, r01+jx1,
                             r10+jx0, r10+jx1, r11+jx0, r11+jx1 };
                float wv[8] = { wzy00*wx0, wzy00*wx1, wzy01*wx0, wzy01*wx1,
                                wzy10*wx0, wzy10*wx1, wzy11*wx0, wzy11*wx1 };
                if (s == 0) {
                    #pragma unroll
                    for (int j = 0; j < 8; j++) { offsPk[j] = o[j]; wgt0[j] = wv[j]; }
                } else {
                    #pragma unroll
                    for (int j = 0; j < 8; j++) { offsPk[j] |= o[j] << 16; wgt1[j] = wv[j]; }
                }
            }

            // ---- merged 16-corner loop: two independent LDS streams per j ----
            #pragma unroll
            for (int j = 0; j < 8; j++) {
                int o0 = offsPk[j] & 0xFFFF;
                int o1 = offsPk[j] >> 16;
                const uint4* p0 = brickq + o0;
                const uint4* p1 = brickq + o1;
                unsigned long long wp0, wp1;
                unsigned int wb0 = __float_as_uint(wgt0[j]);
                unsigned int wb1 = __float_as_uint(wgt1[j]);
                asm("mov.b64 %0, {%1, %1};" : "=l"(wp0) : "r"(wb0));
                asm("mov.b64 %0, {%1, %1};" : "=l"(wp1) : "r"(wb1));
                #pragma unroll
                for (int c8 = 0; c8 < NOCT; c8++) {   // LDS.128 x2, immediate c8*PSV*16
                    uint4 qa = p0[c8 * PSV];
                    uint4 qb = p1[c8 * PSV];
                    {
                        __half2 h0 = *reinterpret_cast<__half2*>(&qa.x);
                        __half2 h1 = *reinterpret_cast<__half2*>(&qa.y);
                        __half2 h2 = *reinterpret_cast<__half2*>(&qa.z);
                        __half2 h3 = *reinterpret_cast<__half2*>(&qa.w);
                        float2 f0 = __half22float2(h0);
                        float2 f1 = __half22float2(h1);
                        float2 f2 = __half22float2(h2);
                        float2 f3 = __half22float2(h3);
                        unsigned long long v0, v1, v2, v3;
                        asm("mov.b64 %0, {%1, %2};" : "=l"(v0) : "f"(f0.x), "f"(f0.y));
                        asm("mov.b64 %0, {%1, %2};" : "=l"(v1) : "f"(f1.x), "f"(f1.y));
                        asm("mov.b64 %0, {%1, %2};" : "=l"(v2) : "f"(f2.x), "f"(f2.y));
                        asm("mov.b64 %0, {%1, %2};" : "=l"(v3) : "f"(f3.x), "f"(f3.y));
                        asm("fma.rn.f32x2 %0, %1, %2, %0;" : "+l"(acc64[4*c8])   : "l"(v0), "l"(wp0));
                        asm("fma.rn.f32x2 %0, %1, %2, %0;" : "+l"(acc64[4*c8+1]) : "l"(v1), "l"(wp0));
                        asm("fma.rn.f32x2 %0, %1, %2, %0;" : "+l"(acc64[4*c8+2]) : "l"(v2), "l"(wp0));
                        asm("fma.rn.f32x2 %0, %1, %2, %0;" : "+l"(acc64[4*c8+3]) : "l"(v3), "l"(wp0));
                    }
                    {
                        __half2 h0 = *reinterpret_cast<__half2*>(&qb.x);
                        __half2 h1 = *reinterpret_cast<__half2*>(&qb.y);
                        __half2 h2 = *reinterpret_cast<__half2*>(&qb.z);
                        __half2 h3 = *reinterpret_cast<__half2*>(&qb.w);
                        float2 f0 = __half22float2(h0);
                        float2 f1 = __half22float2(h1);
                        float2 f2 = __half22float2(h2);
                        float2 f3 = __half22float2(h3);
                        unsigned long long v0, v1, v2, v3;
                        asm("mov.b64 %0, {%1, %2};" : "=l"(v0) : "f"(f0.x), "f"(f0.y));
                        asm("mov.b64 %0, {%1, %2};" : "=l"(v1) : "f"(f1.x), "f"(f1.y));
                        asm("mov.b64 %0, {%1, %2};" : "=l"(v2) : "f"(f2.x), "f"(f2.y));
                        asm("mov.b64 %0, {%1, %2};" : "=l"(v3) : "f"(f3.x), "f"(f3.y));
                        asm("fma.rn.f32x2 %0, %1, %2, %0;" : "+l"(acc64[4*c8])   : "l"(v0), "l"(wp1));
                        asm("fma.rn.f32x2 %0, %1, %2, %0;" : "+l"(acc64[4*c8+1]) : "l"(v1), "l"(wp1));
                        asm("fma.rn.f32x2 %0, %1, %2, %0;" : "+l"(acc64[4*c8+2]) : "l"(v2), "l"(wp1));
                        asm("fma.rn.f32x2 %0, %1, %2, %0;" : "+l"(acc64[4*c8+3]) : "l"(v3), "l"(wp1));
                    }
                }
            }
            #pragma unroll
            for (int p = 0; p < 8; p++) {
                float lo, hi;
                asm("mov.b64 {%0, %1}, %2;" : "=f"(lo), "=f"(hi) : "l"(acc64[p]));
                out[out_base0 + (size_t)(2*p)   * (FEATS*KTOT) + k] = lo;
                out[out_base0 + (size_t)(2*p+1) * (FEATS*KTOT) + k] = hi;
            }
        }
    } else {
        // mode 1: rare oversized bbox -> direct global gathers (full fp32)
        #pragma unroll
        for (int it = 0; it < 2; it++) {
            int k = k0 + it*THREADS + tid;
            float acc[C16];
            #pragma unroll
            for (int c = 0; c < C16; c++) acc[c] = 0.f;

            #pragma unroll
            for (int s = 0; s < 2; s++) {
                const float* wp = W6 + s*3*KTOT + k;
                float w0 = __ldg(wp);
                float w1 = __ldg(wp + KTOT);
                float w2 = __ldg(wp + 2*KTOT);
                float px = fmaf(ax0, w0, fmaf(ax1, w1, fmaf(ax2, w2, bx)));
                float py = fmaf(ay0, w0, fmaf(ay1, w1, fmaf(ay2, w2, by)));
                float pz = fmaf(az0, w0, fmaf(az1, w1, fmaf(az2, w2, bz)));
                float fx = floorf(px), fy = floorf(py), fz = floorf(pz);
                float tx = px - fx, ty = py - fy, tz = pz - fz;
                int jx0 = (int)fx, jy0 = (int)fy, jz0 = (int)fz;
                int jx1 = jx0 + 1, jy1 = jy0 + 1, jz1 = jz0 + 1;
                float wx0 = 1.f - tx, wx1 = tx;
                float wy0 = 1.f - ty, wy1 = ty;
                float wz0 = 1.f - tz, wz1 = tz;
                if ((unsigned)jx0 >= (unsigned)DIM) { wx0 = 0.f; jx0 = 0; }
                if ((unsigned)jx1 >= (unsigned)DIM) { wx1 = 0.f; jx1 = 0; }
                if ((unsigned)jy0 >= (unsigned)DIM) { wy0 = 0.f; jy0 = 0; }
                if ((unsigned)jy1 >= (unsigned)DIM) { wy1 = 0.f; jy1 = 0; }
                if ((unsigned)jz0 >= (unsigned)DIM) { wz0 = 0.f; jz0 = 0; }
                if ((unsigned)jz1 >= (unsigned)DIM) { wz1 = 0.f; jz1 = 0; }
                float sg = s ? -1.f : 1.f;
                float wzy00 = wz0*wy0*sg, wzy01 = wz0*wy1*sg;
                float wzy10 = wz1*wy0*sg, wzy11 = wz1*wy1*sg;
                int r00 = jz0*HW + jy0*DIM, r01 = jz0*HW + jy1*DIM;
                int r10 = jz1*HW + jy0*DIM, r11 = jz1*HW + jy1*DIM;
                int offs[8] = { r00+jx0, r00+jx1, r01+jx0, r01+jx1,
                                r10+jx0, r10+jx1, r11+jx0, r11+jx1 };
                float wgt[8] = { wzy00*wx0, wzy00*wx1, wzy01*wx0, wzy01*wx1,
                                 wzy10*wx0, wzy10*wx1, wzy11*wx0, wzy11*wx1 };
                #pragma unroll
                for (int j = 0; j < 8; j++) {
                    const float* pj = volb + offs[j];
                    float w = wgt[j];
                    #pragma unroll
                    for (int c = 0; c < C16; c++)
                        acc[c] = fmaf(w, __ldg(pj + (size_t)c * DHW), acc[c]);
                }
            }
            #pragma unroll
            for (int c = 0; c < C16; c++)
                out[out_base0 + (size_t)c * (FEATS*KTOT) + k] = acc[c];
        }
    }
}

extern "C" void kernel_launch(void* const* d_in, const int* in_sizes, int n_in,
                              void* d_out, int out_size)
{
    const float* vol  = (const float*)d_in[0];  // [2,16,96,96,96]
    const float* xyz  = (const float*)d_in[1];  // [2,512,3]
    const float* Amat = (const float*)d_in[2];  // [1024,3,3]
    const float* W6   = (const float*)d_in[3];  // [6,1024]
    float* out = (float*)d_out;                 // [2, 16*512, 1024]

    const int nblocks = 2 * 2 * FEATS;          // 2048
    obelisk_kernel<<<nblocks, THREADS>>>(vol, xyz, Amat, W6, out);
}

// round 15
// speedup vs baseline: 1.2830x; 1.1226x over previous
#include <cuda_runtime.h>
#include <cuda_fp16.h>

#define THREADS 256
#define C16 16
#define DIM 96
#define HW (DIM*DIM)
#define DHW (DIM*DIM*DIM)
#define FEATS 512
#define KTOT 1024
#define KPB 512            // k per block (KSPLIT=2)
#define NB 8               // fixed brick edge
// padded strides in uint4 (16B) units: x=1, y=10, z=84
// bank-group(16B): (84*dz + 10*dy + dx) mod 8 = {4dz+2dy+dx} mod 8 -> never 0 for |d|<=1
#define SY 10
#define SZ 84
#define PSV (NB*SZ)        // 672 uint4 per channel-octet slab
#define NOCT 2             // 16 channels = 2 octets (uint4 = 4 x half2)
#define BRICK_E (NOCT*PSV) // 1344 uint4 = 21KB

__global__ void __launch_bounds__(THREADS, 3)
obelisk_kernel(const float* __restrict__ vol,
               const float* __restrict__ xyz,
               const float* __restrict__ Amat,
               const float* __restrict__ W6,
               float* __restrict__ out)
{
    __shared__ uint4 brickq[BRICK_E];   // 21KB static
    __shared__ float sP[12];

    const int tid  = threadIdx.x;
    const int blk  = blockIdx.x;
    const int pt   = blk >> 1;
    const int kh   = blk & 1;
    const int b    = pt >> 9;
    const int f    = pt & (FEATS - 1);
    const int k0   = kh * KPB;

    if (tid == 0) {
        float x0 = xyz[pt*3+0], x1 = xyz[pt*3+1], x2 = xyz[pt*3+2];
        sP[0] = (x0 + 1.f) * 48.f - 0.5f;
        sP[1] = (x1 + 1.f) * 48.f - 0.5f;
        sP[2] = (x2 + 1.f) * 48.f - 0.5f;
        const float* Ar = Amat + pt * 9;
        sP[3] = 48.f*Ar[6]; sP[4]  = 48.f*Ar[7]; sP[5]  = 48.f*Ar[8];  // x row
        sP[6] = 48.f*Ar[3]; sP[7]  = 48.f*Ar[4]; sP[8]  = 48.f*Ar[5];  // y row
        sP[9] = 48.f*Ar[0]; sP[10] = 48.f*Ar[1]; sP[11] = 48.f*Ar[2];  // z row
    }
    __syncthreads();

    const float bx = sP[0], by = sP[1], bz = sP[2];
    const float ax0 = sP[3], ax1 = sP[4],  ax2 = sP[5];
    const float ay0 = sP[6], ay1 = sP[7],  ay2 = sP[8];
    const float az0 = sP[9], az1 = sP[10], az2 = sP[11];

    // ---- Center-anchored brick: [c, c+7] per axis, clamped inside the volume.
    // Offsets are tiny (sigma ~0.42 voxel); +/-3 margin covers ~7 sigma. A per-(k,s)
    // in-brick check + global fallback guarantees correctness regardless.
    int cx = (int)floorf(bx) - 3; cx = min(max(cx, 0), DIM - NB);
    int cy = (int)floorf(by) - 3; cy = min(max(cy, 0), DIM - NB);
    int cz = (int)floorf(bz) - 3; cz = min(max(cz, 0), DIM - NB);

    const float* volb = vol + (size_t)b * C16 * DHW;
    const size_t out_base0 = (((size_t)b * C16) * FEATS + f) * KTOT;

    // --- Brick load: 8x8x8 voxels x 2 channel-octets, fp16x8 (uint4) padded layout ---
    {
        const float* src = volb + (size_t)cz * HW + cy * DIM + cx;
        #pragma unroll
        for (int t = 0; t < (NOCT*NB*NB*NB) / THREADS; t++) {   // 4 iters
            int m = t * THREADS + tid;
            int x  = m & 7;
            int y  = (m >> 3) & 7;
            int z  = (m >> 6) & 7;
            int c8 = m >> 9;
            const float* s0 = src + (size_t)(8*c8) * DHW + z * HW + y * DIM + x;
            __half2 h0 = __floats2half2_rn(__ldg(s0),         __ldg(s0 + DHW));
            __half2 h1 = __floats2half2_rn(__ldg(s0 + 2*DHW), __ldg(s0 + 3*DHW));
            __half2 h2 = __floats2half2_rn(__ldg(s0 + 4*DHW), __ldg(s0 + 5*DHW));
            __half2 h3 = __floats2half2_rn(__ldg(s0 + 6*DHW), __ldg(s0 + 7*DHW));
            uint4 q;
            q.x = *reinterpret_cast<unsigned int*>(&h0);
            q.y = *reinterpret_cast<unsigned int*>(&h1);
            q.z = *reinterpret_cast<unsigned int*>(&h2);
            q.w = *reinterpret_cast<unsigned int*>(&h3);
            brickq[c8 * PSV + z * SZ + y * SY + x] = q;
        }
    }
    __syncthreads();

    // ---------------- Main sampling loop ----------------
    #pragma unroll 1
    for (int it = 0; it < 2; it++) {
        int k = k0 + it*THREADS + tid;
        // 16 fp32 accumulators held as 8 packed f32x2 (64-bit) regs
        unsigned long long acc64[8];
        #pragma unroll
        for (int p = 0; p < 8; p++) acc64[p] = 0ull;

        // load all 6 offset weights up front (batch both LDG latencies)
        float w0a = __ldg(W6 + k);
        float w1a = __ldg(W6 + KTOT + k);
        float w2a = __ldg(W6 + 2*KTOT + k);
        float w0b = __ldg(W6 + 3*KTOT + k);
        float w1b = __ldg(W6 + 4*KTOT + k);
        float w2b = __ldg(W6 + 5*KTOT + k);

        #pragma unroll
        for (int s = 0; s < 2; s++) {
            float w0 = s ? w0b : w0a;
            float w1 = s ? w1b : w1a;
            float w2 = s ? w2b : w2a;
            float px = fmaf(ax0, w0, fmaf(ax1, w1, fmaf(ax2, w2, bx)));
            float py = fmaf(ay0, w0, fmaf(ay1, w1, fmaf(ay2, w2, by)));
            float pz = fmaf(az0, w0, fmaf(az1, w1, fmaf(az2, w2, bz)));
            float fx = floorf(px), fy = floorf(py), fz = floorf(pz);
            float tx = px - fx, ty = py - fy, tz = pz - fz;
            // absolute voxel indices
            int ix0 = (int)fx, iy0 = (int)fy, iz0 = (int)fz;
            int ix1 = ix0 + 1, iy1 = iy0 + 1, iz1 = iz0 + 1;
            float wx0 = 1.f - tx, wx1 = tx;
            float wy0 = 1.f - ty, wy1 = ty;
            float wz0 = 1.f - tz, wz1 = tz;
            // out-of-VOLUME corners: zero weight + clamp index into volume.
            // (clamped index provably lands inside the clamped brick)
            if ((unsigned)ix0 >= DIM) { wx0 = 0.f; ix0 = (ix0 < 0) ? 0 : DIM-1; }
            if ((unsigned)ix1 >= DIM) { wx1 = 0.f; ix1 = (ix1 < 0) ? 0 : DIM-1; }
            if ((unsigned)iy0 >= DIM) { wy0 = 0.f; iy0 = (iy0 < 0) ? 0 : DIM-1; }
            if ((unsigned)iy1 >= DIM) { wy1 = 0.f; iy1 = (iy1 < 0) ? 0 : DIM-1; }
            if ((unsigned)iz0 >= DIM) { wz0 = 0.f; iz0 = (iz0 < 0) ? 0 : DIM-1; }
            if ((unsigned)iz1 >= DIM) { wz1 = 0.f; iz1 = (iz1 < 0) ? 0 : DIM-1; }
            // brick-relative
            int jx0 = ix0 - cx, jx1 = ix1 - cx;
            int jy0 = iy0 - cy, jy1 = iy1 - cy;
            int jz0 = iz0 - cz, jz1 = iz1 - cz;
            float sg = s ? -1.f : 1.f;
            float wzy00 = wz0*wy0*sg, wzy01 = wz0*wy1*sg;
            float wzy10 = wz1*wy0*sg, wzy11 = wz1*wy1*sg;
            float wgt[8] = { wzy00*wx0, wzy00*wx1, wzy01*wx0, wzy01*wx1,
                             wzy10*wx0, wzy10*wx1, wzy11*wx0, wzy11*wx1 };

            if (__builtin_expect((unsigned)(jx0|jx1|jy0|jy1|jz0|jz1) < NB, 1)) {
                // ---- HOT: all 8 corners inside the smem brick ----
                int r00 = jz0*SZ + jy0*SY, r01 = jz0*SZ + jy1*SY;
                int r10 = jz1*SZ + jy0*SY, r11 = jz1*SZ + jy1*SY;
                int offs[8] = { r00+jx0, r00+jx1, r01+jx0, r01+jx1,
                                r10+jx0, r10+jx1, r11+jx0, r11+jx1 };
                #pragma unroll
                for (int j = 0; j < 8; j++) {
                    const uint4* pj = brickq + offs[j];   // one address per corner
                    unsigned long long w2pk;
                    unsigned int wbits = __float_as_uint(wgt[j]);
                    asm("mov.b64 %0, {%1, %1};" : "=l"(w2pk) : "r"(wbits));
                    #pragma unroll
                    for (int c8 = 0; c8 < NOCT; c8++) {   // LDS.128, immediate c8*PSV*16
                        uint4 q = pj[c8 * PSV];
                        __half2 h0 = *reinterpret_cast<__half2*>(&q.x);
                        __half2 h1 = *reinterpret_cast<__half2*>(&q.y);
                        __half2 h2 = *reinterpret_cast<__half2*>(&q.z);
                        __half2 h3 = *reinterpret_cast<__half2*>(&q.w);
                        float2 f0 = __half22float2(h0);
                        float2 f1 = __half22float2(h1);
                        float2 f2 = __half22float2(h2);
                        float2 f3 = __half22float2(h3);
                        unsigned long long v0, v1, v2, v3;
                        asm("mov.b64 %0, {%1, %2};" : "=l"(v0) : "f"(f0.x), "f"(f0.y));
                        asm("mov.b64 %0, {%1, %2};" : "=l"(v1) : "f"(f1.x), "f"(f1.y));
                        asm("mov.b64 %0, {%1, %2};" : "=l"(v2) : "f"(f2.x), "f"(f2.y));
                        asm("mov.b64 %0, {%1, %2};" : "=l"(v3) : "f"(f3.x), "f"(f3.y));
                        asm("fma.rn.f32x2 %0, %1, %2, %0;" : "+l"(acc64[4*c8])   : "l"(v0), "l"(w2pk));
                        asm("fma.rn.f32x2 %0, %1, %2, %0;" : "+l"(acc64[4*c8+1]) : "l"(v1), "l"(w2pk));
                        asm("fma.rn.f32x2 %0, %1, %2, %0;" : "+l"(acc64[4*c8+2]) : "l"(v2), "l"(w2pk));
                        asm("fma.rn.f32x2 %0, %1, %2, %0;" : "+l"(acc64[4*c8+3]) : "l"(v3), "l"(w2pk));
                    }
                }
            } else {
                // ---- COLD (~never): corner outside brick but inside volume ----
                float accf[C16];
                #pragma unroll
                for (int p = 0; p < 8; p++) {
                    float lo, hi;
                    asm("mov.b64 {%0, %1}, %2;" : "=f"(lo), "=f"(hi) : "l"(acc64[p]));
                    accf[2*p] = lo; accf[2*p+1] = hi;
                }
                int r00 = iz0*HW + iy0*DIM, r01 = iz0*HW + iy1*DIM;
                int r10 = iz1*HW + iy0*DIM, r11 = iz1*HW + iy1*DIM;
                int offs[8] = { r00+ix0, r00+ix1, r01+ix0, r01+ix1,
                                r10+ix0, r10+ix1, r11+ix0, r11+ix1 };
                #pragma unroll 1
                for (int j = 0; j < 8; j++) {
                    const float* pj = volb + offs[j];
                    float w = wgt[j];
                    #pragma unroll
                    for (int c = 0; c < C16; c++)
                        accf[c] = fmaf(w, __ldg(pj + (size_t)c * DHW), accf[c]);
                }
                #pragma unroll
                for (int p = 0; p < 8; p++) {
                    asm("mov.b64 %0, {%1, %2};" : "=l"(acc64[p]) : "f"(accf[2*p]), "f"(accf[2*p+1]));
                }
            }
        }
        #pragma unroll
        for (int p = 0; p < 8; p++) {
            float lo, hi;
            asm("mov.b64 {%0, %1}, %2;" : "=f"(lo), "=f"(hi) : "l"(acc64[p]));
            out[out_base0 + (size_t)(2*p)   * (FEATS*KTOT) + k] = lo;
            out[out_base0 + (size_t)(2*p+1) * (FEATS*KTOT) + k] = hi;
        }
    }
}

extern "C" void kernel_launch(void* const* d_in, const int* in_sizes, int n_in,
                              void* d_out, int out_size)
{
    const float* vol  = (const float*)d_in[0];  // [2,16,96,96,96]
    const float* xyz  = (const float*)d_in[1];  // [2,512,3]
    const float* Amat = (const float*)d_in[2];  // [1024,3,3]
    const float* W6   = (const float*)d_in[3];  // [6,1024]
    float* out = (float*)d_out;                 // [2, 16*512, 1024]

    const int nblocks = 2 * 2 * FEATS;          // 2048
    obelisk_kernel<<<nblocks, THREADS>>>(vol, xyz, Amat, W6, out);
}